// round 9
// baseline (speedup 1.0000x reference)
#include <cuda_runtime.h>

#define NN 6144
#define FF 128
#define CC 64
#define HH 4
#define MAXNB 384
#define ATTN_GRID 1536

typedef unsigned long long ull;

#define PACK2(out, lo, hi) \
    asm("mov.b64 %0, {%1, %2};" : "=l"(out) : "f"(lo), "f"(hi))
#define UNPACK2(lo, hi, in) \
    asm("mov.b64 {%0, %1}, %2;" : "=f"(lo), "=f"(hi) : "l"(in))
#define FMA2(d, a, b, c) \
    asm("fma.rn.f32x2 %0, %1, %2, %3;" : "=l"(d) : "l"(a), "l"(b), "l"(c))

// Scratch (allocation-free: __device__ globals)
__device__ float  g_feats [HH * NN * CC];  // X@W1 per head (fp32)
__device__ float  g_feats2[HH * NN * CC];  // X@W2 per head (fp32)
__device__ float4 g_atts4 [NN];            // self logit terms, interleaved [n][h]
__device__ float4 g_attn4 [NN];            // neighbor logit terms, interleaved [n][h]

// ---------------------------------------------------------------------------
// k_proj: tiled SGEMM with f32x2 packed FFMA + att-vector epilogue.
// grid (48, 8): y = head*2 + {0:W1, 1:W2}. BM=128, BN=64(=C), BK=32,
// 256 threads. Thread tile 8 rows x 4 cols, rows packed in pairs (FFMA2).
// ---------------------------------------------------------------------------
__global__ __launch_bounds__(256) void k_proj(
    const float* __restrict__ X,
    const float* __restrict__ W1,
    const float* __restrict__ W2,
    const float* __restrict__ a_self,
    const float* __restrict__ a_neigh)
{
    __shared__ float Xs[32][132];   // [k][m], stride 132 (16B-aligned rows)
    __shared__ float Ws[32][64];    // [k][n]

    const int tid  = threadIdx.x;
    const int n0   = blockIdx.x * 128;
    const int head = blockIdx.y >> 1;
    const int isw2 = blockIdx.y & 1;
    const float* Wsrc = (isw2 ? W2 : W1) + (size_t)head * FF * CC;

    const int tx = tid & 15;
    const int ty = tid >> 4;
    const int c0 = tx * 4;
    const int r0 = ty * 8;

    ull acc[4][4];
    #pragma unroll
    for (int rp = 0; rp < 4; ++rp)
        acc[rp][0] = acc[rp][1] = acc[rp][2] = acc[rp][3] = 0ull;

    for (int kt = 0; kt < 4; ++kt) {
        #pragma unroll
        for (int l = 0; l < 4; ++l) {
            int lin = tid + l * 256;
            int row = lin >> 3;
            int f4  = lin & 7;
            float4 v = *(const float4*)(X + (size_t)(n0 + row) * FF + kt * 32 + f4 * 4);
            Xs[f4 * 4 + 0][row] = v.x;
            Xs[f4 * 4 + 1][row] = v.y;
            Xs[f4 * 4 + 2][row] = v.z;
            Xs[f4 * 4 + 3][row] = v.w;
        }
        #pragma unroll
        for (int l = 0; l < 2; ++l) {
            int lin = tid + l * 256;
            int k  = lin >> 4;
            int c4 = lin & 15;
            *(float4*)&Ws[k][c4 * 4] =
                *(const float4*)(Wsrc + (size_t)(kt * 32 + k) * CC + c4 * 4);
        }
        __syncthreads();

        #pragma unroll 8
        for (int k = 0; k < 32; ++k) {
            ulonglong2 xa = *(const ulonglong2*)&Xs[k][r0];
            ulonglong2 xb = *(const ulonglong2*)&Xs[k][r0 + 4];
            float4 w = *(const float4*)&Ws[k][c0];
            ull wx, wy, wz, ww;
            PACK2(wx, w.x, w.x);
            PACK2(wy, w.y, w.y);
            PACK2(wz, w.z, w.z);
            PACK2(ww, w.w, w.w);
            FMA2(acc[0][0], xa.x, wx, acc[0][0]);
            FMA2(acc[0][1], xa.x, wy, acc[0][1]);
            FMA2(acc[0][2], xa.x, wz, acc[0][2]);
            FMA2(acc[0][3], xa.x, ww, acc[0][3]);
            FMA2(acc[1][0], xa.y, wx, acc[1][0]);
            FMA2(acc[1][1], xa.y, wy, acc[1][1]);
            FMA2(acc[1][2], xa.y, wz, acc[1][2]);
            FMA2(acc[1][3], xa.y, ww, acc[1][3]);
            FMA2(acc[2][0], xb.x, wx, acc[2][0]);
            FMA2(acc[2][1], xb.x, wy, acc[2][1]);
            FMA2(acc[2][2], xb.x, wz, acc[2][2]);
            FMA2(acc[2][3], xb.x, ww, acc[2][3]);
            FMA2(acc[3][0], xb.y, wx, acc[3][0]);
            FMA2(acc[3][1], xb.y, wy, acc[3][1]);
            FMA2(acc[3][2], xb.y, wz, acc[3][2]);
            FMA2(acc[3][3], xb.y, ww, acc[3][3]);
        }
        __syncthreads();
    }

    float* dst = (isw2 ? g_feats2 : g_feats)
               + ((size_t)head * NN + n0 + r0) * CC + c0;
    const float4 as = *(const float4*)(a_self  + head * CC + c0);
    const float4 an = *(const float4*)(a_neigh + head * CC + c0);

    #pragma unroll
    for (int rp = 0; rp < 4; ++rp) {
        float lo0, hi0, lo1, hi1, lo2, hi2, lo3, hi3;
        UNPACK2(lo0, hi0, acc[rp][0]);
        UNPACK2(lo1, hi1, acc[rp][1]);
        UNPACK2(lo2, hi2, acc[rp][2]);
        UNPACK2(lo3, hi3, acc[rp][3]);
        *(float4*)(dst + (size_t)(2 * rp) * CC)     = make_float4(lo0, lo1, lo2, lo3);
        *(float4*)(dst + (size_t)(2 * rp + 1) * CC) = make_float4(hi0, hi1, hi2, hi3);

        if (!isw2) {
            float s0 = lo0 * as.x + lo1 * as.y + lo2 * as.z + lo3 * as.w;
            float t0 = lo0 * an.x + lo1 * an.y + lo2 * an.z + lo3 * an.w;
            float s1 = hi0 * as.x + hi1 * as.y + hi2 * as.z + hi3 * as.w;
            float t1 = hi0 * an.x + hi1 * an.y + hi2 * an.z + hi3 * an.w;
            #pragma unroll
            for (int o = 8; o; o >>= 1) {
                s0 += __shfl_xor_sync(0xffffffffu, s0, o);
                t0 += __shfl_xor_sync(0xffffffffu, t0, o);
                s1 += __shfl_xor_sync(0xffffffffu, s1, o);
                t1 += __shfl_xor_sync(0xffffffffu, t1, o);
            }
            if (tx == 0) {
                ((float*)g_atts4)[(n0 + r0 + 2 * rp) * 4 + head]     = s0;
                ((float*)g_attn4)[(n0 + r0 + 2 * rp) * 4 + head]     = t0;
                ((float*)g_atts4)[(n0 + r0 + 2 * rp + 1) * 4 + head] = s1;
                ((float*)g_attn4)[(n0 + r0 + 2 * rp + 1) * 4 + head] = t1;
            }
        }
    }
}

// ---------------------------------------------------------------------------
// k_attn: persistent fused A-scan + sparse softmax-aggregate.
// 1536 CTAs x 128 threads, grid-stride over rows (4 rows/CTA). Each row body
// first issues register-free L2 prefetches for the NEXT row's A data, so the
// current row's scan loads (prefetched one body earlier) hit L2 and HBM
// streams continuously instead of stalling per-phase.
// ---------------------------------------------------------------------------
__global__ __launch_bounds__(128) void k_attn(
    const float* __restrict__ A,
    const float* __restrict__ bias,
    float* __restrict__ out)
{
    __shared__ int   s_idx[MAXNB + 4];       // byte offsets (col * 256)
    __shared__ float s_e[HH][MAXNB + 4];
    __shared__ int   s_wsum[4];
    __shared__ float s_redm[4][4];           // [warp][head] max partials
    __shared__ float s_reds[4][4];           // [warp][head] sum partials
    __shared__ float s_out[HH][CC];

    const int tid  = threadIdx.x;
    const int lane = tid & 31;
    const int warp = tid >> 5;

    for (int i = blockIdx.x; i < NN; i += ATTN_GRID) {

        // --- L2 prefetch of NEXT row's A chunk (register-free) ---
        if (i + ATTN_GRID < NN) {
            const char* pn = (const char*)(A + (size_t)(i + ATTN_GRID) * NN + 4 * tid);
            #pragma unroll
            for (int k = 0; k < 12; ++k)
                asm volatile("prefetch.global.L2 [%0];" :: "l"(pn + (size_t)k * 2048));
        }

        const float* Ai = A + (size_t)i * NN;

        // --- coalesced scan (prefetched -> mostly L2 hits) ---
        ull mask = 0ull;
        #pragma unroll
        for (int k = 0; k < 12; ++k) {
            float4 v = *(const float4*)(Ai + 4 * tid + 512 * k);
            unsigned m = (unsigned)(v.x != 0.f)
                       | ((unsigned)(v.y != 0.f) << 1)
                       | ((unsigned)(v.z != 0.f) << 2)
                       | ((unsigned)(v.w != 0.f) << 3);
            mask |= (ull)m << (4 * k);
        }
        const int lc = __popcll(mask);

        // --- warp shfl scan + cross-warp combine ---
        int v = lc;
        #pragma unroll
        for (int o = 1; o < 32; o <<= 1) {
            int u = __shfl_up_sync(0xffffffffu, v, o);
            if (lane >= o) v += u;
        }
        if (lane == 31) s_wsum[warp] = v;
        __syncthreads();
        int base = 0;
        #pragma unroll
        for (int w = 0; w < 4; ++w)
            if (w < warp) base += s_wsum[w];
        int cnt = s_wsum[0] + s_wsum[1] + s_wsum[2] + s_wsum[3];
        if (cnt > MAXNB) cnt = MAXNB;

        // --- compaction: store BYTE offsets (col << 8 = col * CC * 4) ---
        int p = base + v - lc;
        ull m2 = mask;
        while (m2) {
            int b = __ffsll((long long)m2) - 1;
            m2 &= m2 - 1;
            int col = 4 * tid + 512 * (b >> 2) + (b & 3);
            if (p < MAXNB) s_idx[p] = col << 8;
            ++p;
        }
        if (tid < 3)  s_idx[cnt + tid] = 0;                  // pad (int4 reads)
        if (tid < 12) s_e[tid & 3][cnt + (tid >> 2)] = 0.f;  // pad (float4 reads)
        __syncthreads();

        // --- logit pass: ONE float4 gather per neighbor serves all 4 heads ---
        const float4 si4 = g_atts4[i];
        float m0 = -1e30f, m1 = -1e30f, m2f = -1e30f, m3 = -1e30f;
        for (int j = tid; j < cnt; j += 128) {
            int off = s_idx[j];
            float4 an = *(const float4*)((const char*)g_attn4 + (off >> 4));
            float l0 = si4.x + an.x;  l0 = (l0 > 0.f) ? l0 : 0.2f * l0;
            float l1 = si4.y + an.y;  l1 = (l1 > 0.f) ? l1 : 0.2f * l1;
            float l2 = si4.z + an.z;  l2 = (l2 > 0.f) ? l2 : 0.2f * l2;
            float l3 = si4.w + an.w;  l3 = (l3 > 0.f) ? l3 : 0.2f * l3;
            s_e[0][j] = l0;  s_e[1][j] = l1;  s_e[2][j] = l2;  s_e[3][j] = l3;
            m0 = fmaxf(m0, l0);  m1 = fmaxf(m1, l1);
            m2f = fmaxf(m2f, l2);  m3 = fmaxf(m3, l3);
        }
        #pragma unroll
        for (int o = 16; o; o >>= 1) {
            m0  = fmaxf(m0,  __shfl_xor_sync(0xffffffffu, m0,  o));
            m1  = fmaxf(m1,  __shfl_xor_sync(0xffffffffu, m1,  o));
            m2f = fmaxf(m2f, __shfl_xor_sync(0xffffffffu, m2f, o));
            m3  = fmaxf(m3,  __shfl_xor_sync(0xffffffffu, m3,  o));
        }
        if (lane == 0)
            *(float4*)&s_redm[warp][0] = make_float4(m0, m1, m2f, m3);
        __syncthreads();
        {
            float4 a = *(float4*)&s_redm[0][0];
            float4 b = *(float4*)&s_redm[1][0];
            float4 c = *(float4*)&s_redm[2][0];
            float4 d = *(float4*)&s_redm[3][0];
            m0  = fmaxf(fmaxf(a.x, b.x), fmaxf(c.x, d.x));
            m1  = fmaxf(fmaxf(a.y, b.y), fmaxf(c.y, d.y));
            m2f = fmaxf(fmaxf(a.z, b.z), fmaxf(c.z, d.z));
            m3  = fmaxf(fmaxf(a.w, b.w), fmaxf(c.w, d.w));
        }

        // --- exp pass (smem only) ---
        float q0 = 0.f, q1 = 0.f, q2 = 0.f, q3 = 0.f;
        for (int j = tid; j < cnt; j += 128) {
            float e0 = __expf(s_e[0][j] - m0);   s_e[0][j] = e0;  q0 += e0;
            float e1 = __expf(s_e[1][j] - m1);   s_e[1][j] = e1;  q1 += e1;
            float e2 = __expf(s_e[2][j] - m2f);  s_e[2][j] = e2;  q2 += e2;
            float e3 = __expf(s_e[3][j] - m3);   s_e[3][j] = e3;  q3 += e3;
        }
        #pragma unroll
        for (int o = 16; o; o >>= 1) {
            q0 += __shfl_xor_sync(0xffffffffu, q0, o);
            q1 += __shfl_xor_sync(0xffffffffu, q1, o);
            q2 += __shfl_xor_sync(0xffffffffu, q2, o);
            q3 += __shfl_xor_sync(0xffffffffu, q3, o);
        }
        if (lane == 0)
            *(float4*)&s_reds[warp][0] = make_float4(q0, q1, q2, q3);
        __syncthreads();

        // --- gather-aggregate: warp h owns head h; float2 per neighbor ---
        const int h = warp;
        const float inv = 1.f / (s_reds[0][h] + s_reds[1][h] + s_reds[2][h] + s_reds[3][h]);
        const char* fh = (const char*)(g_feats + (size_t)h * NN * CC) + lane * 8;
        float acc0 = 0.f, acc1 = 0.f;
        for (int j = 0; j < cnt; j += 4) {
            float4 e4 = *(const float4*)&s_e[h][j];
            int4   o4 = *(const int4*)&s_idx[j];
            float2 f0 = *(const float2*)(fh + o4.x);
            float2 f1 = *(const float2*)(fh + o4.y);
            float2 f2 = *(const float2*)(fh + o4.z);
            float2 f3 = *(const float2*)(fh + o4.w);
            acc0 += e4.x * f0.x;   acc1 += e4.x * f0.y;
            acc0 += e4.y * f1.x;   acc1 += e4.y * f1.y;
            acc0 += e4.z * f2.x;   acc1 += e4.z * f2.y;
            acc0 += e4.w * f3.x;   acc1 += e4.w * f3.y;
        }
        s_out[h][2 * lane]     = acc0 * inv;
        s_out[h][2 * lane + 1] = acc1 * inv;
        __syncthreads();

        if (tid < CC) {
            float b = 0.f;
            #pragma unroll
            for (int hh = 0; hh < HH; ++hh)
                b += g_feats2[((size_t)hh * NN + i) * CC + tid] + bias[hh * CC + tid];
            float o = 0.25f * b
                    + 0.25f * (s_out[0][tid] + s_out[1][tid] + s_out[2][tid] + s_out[3][tid]);
            out[(size_t)i * CC + tid] = (o > 0.f) ? o : 0.f;
        }
        // no barrier needed here: next iteration's first smem writes
        // (s_wsum, s_idx) are not read by this iteration's epilogue, and the
        // next __syncthreads() re-converges all threads before any use.
    }
}

// ---------------------------------------------------------------------------
extern "C" void kernel_launch(void* const* d_in, const int* in_sizes, int n_in,
                              void* d_out, int out_size)
{
    const float* X       = (const float*)d_in[0];
    const float* A       = (const float*)d_in[1];
    const float* W1      = (const float*)d_in[2];
    const float* W2      = (const float*)d_in[3];
    const float* a_self  = (const float*)d_in[4];
    const float* a_neigh = (const float*)d_in[5];
    const float* bias    = (const float*)d_in[6];
    float* out = (float*)d_out;

    k_proj<<<dim3(48, 8), 256>>>(X, W1, W2, a_self, a_neigh);
    k_attn<<<ATTN_GRID,   128>>>(A, bias, out);
}

// round 10
// speedup vs baseline: 1.0273x; 1.0273x over previous
#include <cuda_runtime.h>

#define NN 6144
#define FF 128
#define CC 64
#define HH 4
#define MAXNB 384
#define ROWS_PER_CTA 4
#define ATTN_GRID (NN / ROWS_PER_CTA)

typedef unsigned long long ull;

#define PACK2(out, lo, hi) \
    asm("mov.b64 %0, {%1, %2};" : "=l"(out) : "f"(lo), "f"(hi))
#define UNPACK2(lo, hi, in) \
    asm("mov.b64 {%0, %1}, %2;" : "=f"(lo), "=f"(hi) : "l"(in))
#define FMA2(d, a, b, c) \
    asm("fma.rn.f32x2 %0, %1, %2, %3;" : "=l"(d) : "l"(a), "l"(b), "l"(c))

// Scratch (allocation-free: __device__ globals)
__device__ float  g_feats [HH * NN * CC];  // X@W1 per head (fp32)
__device__ float  g_feats2[HH * NN * CC];  // X@W2 per head (fp32)
__device__ float4 g_atts4 [NN];            // self logit terms, interleaved [n][h]
__device__ float4 g_attn4 [NN];            // neighbor logit terms, interleaved [n][h]

// ---------------------------------------------------------------------------
// k_proj: tiled SGEMM with f32x2 packed FFMA + att-vector epilogue.
// (unchanged from R8 — 20.5us, protected)
// ---------------------------------------------------------------------------
__global__ __launch_bounds__(256) void k_proj(
    const float* __restrict__ X,
    const float* __restrict__ W1,
    const float* __restrict__ W2,
    const float* __restrict__ a_self,
    const float* __restrict__ a_neigh)
{
    __shared__ float Xs[32][132];
    __shared__ float Ws[32][64];

    const int tid  = threadIdx.x;
    const int n0   = blockIdx.x * 128;
    const int head = blockIdx.y >> 1;
    const int isw2 = blockIdx.y & 1;
    const float* Wsrc = (isw2 ? W2 : W1) + (size_t)head * FF * CC;

    const int tx = tid & 15;
    const int ty = tid >> 4;
    const int c0 = tx * 4;
    const int r0 = ty * 8;

    ull acc[4][4];
    #pragma unroll
    for (int rp = 0; rp < 4; ++rp)
        acc[rp][0] = acc[rp][1] = acc[rp][2] = acc[rp][3] = 0ull;

    for (int kt = 0; kt < 4; ++kt) {
        #pragma unroll
        for (int l = 0; l < 4; ++l) {
            int lin = tid + l * 256;
            int row = lin >> 3;
            int f4  = lin & 7;
            float4 v = *(const float4*)(X + (size_t)(n0 + row) * FF + kt * 32 + f4 * 4);
            Xs[f4 * 4 + 0][row] = v.x;
            Xs[f4 * 4 + 1][row] = v.y;
            Xs[f4 * 4 + 2][row] = v.z;
            Xs[f4 * 4 + 3][row] = v.w;
        }
        #pragma unroll
        for (int l = 0; l < 2; ++l) {
            int lin = tid + l * 256;
            int k  = lin >> 4;
            int c4 = lin & 15;
            *(float4*)&Ws[k][c4 * 4] =
                *(const float4*)(Wsrc + (size_t)(kt * 32 + k) * CC + c4 * 4);
        }
        __syncthreads();

        #pragma unroll 8
        for (int k = 0; k < 32; ++k) {
            ulonglong2 xa = *(const ulonglong2*)&Xs[k][r0];
            ulonglong2 xb = *(const ulonglong2*)&Xs[k][r0 + 4];
            float4 w = *(const float4*)&Ws[k][c0];
            ull wx, wy, wz, ww;
            PACK2(wx, w.x, w.x);
            PACK2(wy, w.y, w.y);
            PACK2(wz, w.z, w.z);
            PACK2(ww, w.w, w.w);
            FMA2(acc[0][0], xa.x, wx, acc[0][0]);
            FMA2(acc[0][1], xa.x, wy, acc[0][1]);
            FMA2(acc[0][2], xa.x, wz, acc[0][2]);
            FMA2(acc[0][3], xa.x, ww, acc[0][3]);
            FMA2(acc[1][0], xa.y, wx, acc[1][0]);
            FMA2(acc[1][1], xa.y, wy, acc[1][1]);
            FMA2(acc[1][2], xa.y, wz, acc[1][2]);
            FMA2(acc[1][3], xa.y, ww, acc[1][3]);
            FMA2(acc[2][0], xb.x, wx, acc[2][0]);
            FMA2(acc[2][1], xb.x, wy, acc[2][1]);
            FMA2(acc[2][2], xb.x, wz, acc[2][2]);
            FMA2(acc[2][3], xb.x, ww, acc[2][3]);
            FMA2(acc[3][0], xb.y, wx, acc[3][0]);
            FMA2(acc[3][1], xb.y, wy, acc[3][1]);
            FMA2(acc[3][2], xb.y, wz, acc[3][2]);
            FMA2(acc[3][3], xb.y, ww, acc[3][3]);
        }
        __syncthreads();
    }

    float* dst = (isw2 ? g_feats2 : g_feats)
               + ((size_t)head * NN + n0 + r0) * CC + c0;
    const float4 as = *(const float4*)(a_self  + head * CC + c0);
    const float4 an = *(const float4*)(a_neigh + head * CC + c0);

    #pragma unroll
    for (int rp = 0; rp < 4; ++rp) {
        float lo0, hi0, lo1, hi1, lo2, hi2, lo3, hi3;
        UNPACK2(lo0, hi0, acc[rp][0]);
        UNPACK2(lo1, hi1, acc[rp][1]);
        UNPACK2(lo2, hi2, acc[rp][2]);
        UNPACK2(lo3, hi3, acc[rp][3]);
        *(float4*)(dst + (size_t)(2 * rp) * CC)     = make_float4(lo0, lo1, lo2, lo3);
        *(float4*)(dst + (size_t)(2 * rp + 1) * CC) = make_float4(hi0, hi1, hi2, hi3);

        if (!isw2) {
            float s0 = lo0 * as.x + lo1 * as.y + lo2 * as.z + lo3 * as.w;
            float t0 = lo0 * an.x + lo1 * an.y + lo2 * an.z + lo3 * an.w;
            float s1 = hi0 * as.x + hi1 * as.y + hi2 * as.z + hi3 * as.w;
            float t1 = hi0 * an.x + hi1 * an.y + hi2 * an.z + hi3 * an.w;
            #pragma unroll
            for (int o = 8; o; o >>= 1) {
                s0 += __shfl_xor_sync(0xffffffffu, s0, o);
                t0 += __shfl_xor_sync(0xffffffffu, t0, o);
                s1 += __shfl_xor_sync(0xffffffffu, s1, o);
                t1 += __shfl_xor_sync(0xffffffffu, t1, o);
            }
            if (tx == 0) {
                ((float*)g_atts4)[(n0 + r0 + 2 * rp) * 4 + head]     = s0;
                ((float*)g_attn4)[(n0 + r0 + 2 * rp) * 4 + head]     = t0;
                ((float*)g_atts4)[(n0 + r0 + 2 * rp + 1) * 4 + head] = s1;
                ((float*)g_attn4)[(n0 + r0 + 2 * rp + 1) * 4 + head] = t1;
            }
        }
    }
}

// ---------------------------------------------------------------------------
// k_attn: fused sparse softmax-aggregate with cp.async double-buffered A-scan.
// 1536 CTAs x 128 threads, 4 adjacent rows each. The NEXT row's A-data
// streams into smem via cp.async WHILE the current row's compact/logit/exp/
// gather phases run. Thread X reads only bytes thread X wrote, so
// cp.async.wait_group per-thread suffices — no extra barriers.
// ---------------------------------------------------------------------------
__global__ __launch_bounds__(128) void k_attn(
    const float* __restrict__ A,
    const float* __restrict__ bias,
    float* __restrict__ out)
{
    __shared__ float4 s_buf[128 * 12];       // 24KB A-row staging buffer
    __shared__ int    s_idx[MAXNB + 4];      // byte offsets (col * 256)
    __shared__ float  s_e[HH][MAXNB + 4];
    __shared__ int    s_wsum[4];
    __shared__ float  s_redm[4][4];
    __shared__ float  s_reds[4][4];
    __shared__ float  s_out[HH][CC];

    const int tid  = threadIdx.x;
    const int lane = tid & 31;
    const int warp = tid >> 5;

    // per-thread smem slice base (16B at [tid], stride 2048B per k)
    unsigned sb = (unsigned)__cvta_generic_to_shared(s_buf) + tid * 16;

    int i = blockIdx.x * ROWS_PER_CTA;

    // prologue: stage row i
    {
        const char* gsrc = (const char*)(A + (size_t)i * NN) + tid * 16;
        #pragma unroll
        for (int k = 0; k < 12; ++k)
            asm volatile("cp.async.cg.shared.global [%0], [%1], 16;"
                         :: "r"(sb + k * 2048), "l"(gsrc + (size_t)k * 2048));
        asm volatile("cp.async.commit_group;" ::: "memory");
    }

    for (int t = 0; t < ROWS_PER_CTA; ++t, ++i) {
        // wait for this thread's staged row, consume own slice into bitmask
        asm volatile("cp.async.wait_group 0;" ::: "memory");
        ull mask = 0ull;
        #pragma unroll
        for (int k = 0; k < 12; ++k) {
            float4 v = s_buf[tid + 128 * k];
            unsigned m = (unsigned)(v.x != 0.f)
                       | ((unsigned)(v.y != 0.f) << 1)
                       | ((unsigned)(v.z != 0.f) << 2)
                       | ((unsigned)(v.w != 0.f) << 3);
            mask |= (ull)m << (4 * k);
        }

        // immediately stage the NEXT row into our own (just-consumed) slice;
        // it streams in while the phases below run.
        if (t + 1 < ROWS_PER_CTA) {
            const char* gsrc = (const char*)(A + (size_t)(i + 1) * NN) + tid * 16;
            #pragma unroll
            for (int k = 0; k < 12; ++k)
                asm volatile("cp.async.cg.shared.global [%0], [%1], 16;"
                             :: "r"(sb + k * 2048), "l"(gsrc + (size_t)k * 2048));
            asm volatile("cp.async.commit_group;" ::: "memory");
        }

        const int lc = __popcll(mask);

        // --- warp shfl scan + cross-warp combine ---
        int v = lc;
        #pragma unroll
        for (int o = 1; o < 32; o <<= 1) {
            int u = __shfl_up_sync(0xffffffffu, v, o);
            if (lane >= o) v += u;
        }
        if (lane == 31) s_wsum[warp] = v;
        __syncthreads();
        int base = 0;
        #pragma unroll
        for (int w = 0; w < 4; ++w)
            if (w < warp) base += s_wsum[w];
        int cnt = s_wsum[0] + s_wsum[1] + s_wsum[2] + s_wsum[3];
        if (cnt > MAXNB) cnt = MAXNB;

        // --- compaction: store BYTE offsets (col << 8 = col * CC * 4) ---
        int p = base + v - lc;
        ull m2 = mask;
        while (m2) {
            int b = __ffsll((long long)m2) - 1;
            m2 &= m2 - 1;
            int col = 4 * tid + 512 * (b >> 2) + (b & 3);
            if (p < MAXNB) s_idx[p] = col << 8;
            ++p;
        }
        if (tid < 3)  s_idx[cnt + tid] = 0;
        if (tid < 12) s_e[tid & 3][cnt + (tid >> 2)] = 0.f;
        __syncthreads();

        // --- logit pass: ONE float4 gather per neighbor serves all 4 heads ---
        const float4 si4 = g_atts4[i];
        float m0 = -1e30f, m1 = -1e30f, m2f = -1e30f, m3 = -1e30f;
        for (int j = tid; j < cnt; j += 128) {
            int off = s_idx[j];
            float4 an = *(const float4*)((const char*)g_attn4 + (off >> 4));
            float l0 = si4.x + an.x;  l0 = (l0 > 0.f) ? l0 : 0.2f * l0;
            float l1 = si4.y + an.y;  l1 = (l1 > 0.f) ? l1 : 0.2f * l1;
            float l2 = si4.z + an.z;  l2 = (l2 > 0.f) ? l2 : 0.2f * l2;
            float l3 = si4.w + an.w;  l3 = (l3 > 0.f) ? l3 : 0.2f * l3;
            s_e[0][j] = l0;  s_e[1][j] = l1;  s_e[2][j] = l2;  s_e[3][j] = l3;
            m0 = fmaxf(m0, l0);  m1 = fmaxf(m1, l1);
            m2f = fmaxf(m2f, l2);  m3 = fmaxf(m3, l3);
        }
        #pragma unroll
        for (int o = 16; o; o >>= 1) {
            m0  = fmaxf(m0,  __shfl_xor_sync(0xffffffffu, m0,  o));
            m1  = fmaxf(m1,  __shfl_xor_sync(0xffffffffu, m1,  o));
            m2f = fmaxf(m2f, __shfl_xor_sync(0xffffffffu, m2f, o));
            m3  = fmaxf(m3,  __shfl_xor_sync(0xffffffffu, m3,  o));
        }
        if (lane == 0)
            *(float4*)&s_redm[warp][0] = make_float4(m0, m1, m2f, m3);
        __syncthreads();
        {
            float4 a = *(float4*)&s_redm[0][0];
            float4 b = *(float4*)&s_redm[1][0];
            float4 c = *(float4*)&s_redm[2][0];
            float4 d = *(float4*)&s_redm[3][0];
            m0  = fmaxf(fmaxf(a.x, b.x), fmaxf(c.x, d.x));
            m1  = fmaxf(fmaxf(a.y, b.y), fmaxf(c.y, d.y));
            m2f = fmaxf(fmaxf(a.z, b.z), fmaxf(c.z, d.z));
            m3  = fmaxf(fmaxf(a.w, b.w), fmaxf(c.w, d.w));
        }

        // --- exp pass (smem only) ---
        float q0 = 0.f, q1 = 0.f, q2 = 0.f, q3 = 0.f;
        for (int j = tid; j < cnt; j += 128) {
            float e0 = __expf(s_e[0][j] - m0);   s_e[0][j] = e0;  q0 += e0;
            float e1 = __expf(s_e[1][j] - m1);   s_e[1][j] = e1;  q1 += e1;
            float e2 = __expf(s_e[2][j] - m2f);  s_e[2][j] = e2;  q2 += e2;
            float e3 = __expf(s_e[3][j] - m3);   s_e[3][j] = e3;  q3 += e3;
        }
        #pragma unroll
        for (int o = 16; o; o >>= 1) {
            q0 += __shfl_xor_sync(0xffffffffu, q0, o);
            q1 += __shfl_xor_sync(0xffffffffu, q1, o);
            q2 += __shfl_xor_sync(0xffffffffu, q2, o);
            q3 += __shfl_xor_sync(0xffffffffu, q3, o);
        }
        if (lane == 0)
            *(float4*)&s_reds[warp][0] = make_float4(q0, q1, q2, q3);
        __syncthreads();

        // --- gather-aggregate: warp h owns head h; float2 per neighbor ---
        const int h = warp;
        const float inv = 1.f / (s_reds[0][h] + s_reds[1][h] + s_reds[2][h] + s_reds[3][h]);
        const char* fh = (const char*)(g_feats + (size_t)h * NN * CC) + lane * 8;
        float acc0 = 0.f, acc1 = 0.f;
        for (int j = 0; j < cnt; j += 4) {
            float4 e4 = *(const float4*)&s_e[h][j];
            int4   o4 = *(const int4*)&s_idx[j];
            float2 f0 = *(const float2*)(fh + o4.x);
            float2 f1 = *(const float2*)(fh + o4.y);
            float2 f2 = *(const float2*)(fh + o4.z);
            float2 f3 = *(const float2*)(fh + o4.w);
            acc0 += e4.x * f0.x;   acc1 += e4.x * f0.y;
            acc0 += e4.y * f1.x;   acc1 += e4.y * f1.y;
            acc0 += e4.z * f2.x;   acc1 += e4.z * f2.y;
            acc0 += e4.w * f3.x;   acc1 += e4.w * f3.y;
        }
        s_out[h][2 * lane]     = acc0 * inv;
        s_out[h][2 * lane + 1] = acc1 * inv;
        __syncthreads();

        if (tid < CC) {
            float b = 0.f;
            #pragma unroll
            for (int hh = 0; hh < HH; ++hh)
                b += g_feats2[((size_t)hh * NN + i) * CC + tid] + bias[hh * CC + tid];
            float o = 0.25f * b
                    + 0.25f * (s_out[0][tid] + s_out[1][tid] + s_out[2][tid] + s_out[3][tid]);
            out[(size_t)i * CC + tid] = (o > 0.f) ? o : 0.f;
        }
    }
}

// ---------------------------------------------------------------------------
extern "C" void kernel_launch(void* const* d_in, const int* in_sizes, int n_in,
                              void* d_out, int out_size)
{
    const float* X       = (const float*)d_in[0];
    const float* A       = (const float*)d_in[1];
    const float* W1      = (const float*)d_in[2];
    const float* W2      = (const float*)d_in[3];
    const float* a_self  = (const float*)d_in[4];
    const float* a_neigh = (const float*)d_in[5];
    const float* bias    = (const float*)d_in[6];
    float* out = (float*)d_out;

    k_proj<<<dim3(48, 8), 256>>>(X, W1, W2, a_self, a_neigh);
    k_attn<<<ATTN_GRID,   128>>>(A, bias, out);
}

// round 11
// speedup vs baseline: 1.1758x; 1.1446x over previous
#include <cuda_runtime.h>

#define NN 6144
#define FF 128
#define CC 64
#define HH 4
#define MAXNB 384

typedef unsigned long long ull;

#define PACK2(out, lo, hi) \
    asm("mov.b64 %0, {%1, %2};" : "=l"(out) : "f"(lo), "f"(hi))
#define UNPACK2(lo, hi, in) \
    asm("mov.b64 {%0, %1}, %2;" : "=f"(lo), "=f"(hi) : "l"(in))
#define FMA2(d, a, b, c) \
    asm("fma.rn.f32x2 %0, %1, %2, %3;" : "=l"(d) : "l"(a), "l"(b), "l"(c))

// Scratch (allocation-free: __device__ globals)
__device__ float  g_featsI[NN * HH * CC];  // X@W1, head-interleaved [n][h][c]
__device__ float  g_feats2[HH * NN * CC];  // X@W2 per head (fp32)
__device__ float4 g_atts4 [NN];            // self logit terms, interleaved [n][h]
__device__ float4 g_attn4 [NN];            // neighbor logit terms, interleaved [n][h]

// ---------------------------------------------------------------------------
// k_proj: tiled SGEMM with f32x2 packed FFMA + att-vector epilogue.
// W1 output goes to the head-interleaved layout [n][h][c] (same STG.128
// pattern, different row stride); W2 output unchanged.
// ---------------------------------------------------------------------------
__global__ __launch_bounds__(256) void k_proj(
    const float* __restrict__ X,
    const float* __restrict__ W1,
    const float* __restrict__ W2,
    const float* __restrict__ a_self,
    const float* __restrict__ a_neigh)
{
    __shared__ float Xs[32][132];
    __shared__ float Ws[32][64];

    const int tid  = threadIdx.x;
    const int n0   = blockIdx.x * 128;
    const int head = blockIdx.y >> 1;
    const int isw2 = blockIdx.y & 1;
    const float* Wsrc = (isw2 ? W2 : W1) + (size_t)head * FF * CC;

    const int tx = tid & 15;
    const int ty = tid >> 4;
    const int c0 = tx * 4;
    const int r0 = ty * 8;

    ull acc[4][4];
    #pragma unroll
    for (int rp = 0; rp < 4; ++rp)
        acc[rp][0] = acc[rp][1] = acc[rp][2] = acc[rp][3] = 0ull;

    for (int kt = 0; kt < 4; ++kt) {
        #pragma unroll
        for (int l = 0; l < 4; ++l) {
            int lin = tid + l * 256;
            int row = lin >> 3;
            int f4  = lin & 7;
            float4 v = *(const float4*)(X + (size_t)(n0 + row) * FF + kt * 32 + f4 * 4);
            Xs[f4 * 4 + 0][row] = v.x;
            Xs[f4 * 4 + 1][row] = v.y;
            Xs[f4 * 4 + 2][row] = v.z;
            Xs[f4 * 4 + 3][row] = v.w;
        }
        #pragma unroll
        for (int l = 0; l < 2; ++l) {
            int lin = tid + l * 256;
            int k  = lin >> 4;
            int c4 = lin & 15;
            *(float4*)&Ws[k][c4 * 4] =
                *(const float4*)(Wsrc + (size_t)(kt * 32 + k) * CC + c4 * 4);
        }
        __syncthreads();

        #pragma unroll 8
        for (int k = 0; k < 32; ++k) {
            ulonglong2 xa = *(const ulonglong2*)&Xs[k][r0];
            ulonglong2 xb = *(const ulonglong2*)&Xs[k][r0 + 4];
            float4 w = *(const float4*)&Ws[k][c0];
            ull wx, wy, wz, ww;
            PACK2(wx, w.x, w.x);
            PACK2(wy, w.y, w.y);
            PACK2(wz, w.z, w.z);
            PACK2(ww, w.w, w.w);
            FMA2(acc[0][0], xa.x, wx, acc[0][0]);
            FMA2(acc[0][1], xa.x, wy, acc[0][1]);
            FMA2(acc[0][2], xa.x, wz, acc[0][2]);
            FMA2(acc[0][3], xa.x, ww, acc[0][3]);
            FMA2(acc[1][0], xa.y, wx, acc[1][0]);
            FMA2(acc[1][1], xa.y, wy, acc[1][1]);
            FMA2(acc[1][2], xa.y, wz, acc[1][2]);
            FMA2(acc[1][3], xa.y, ww, acc[1][3]);
            FMA2(acc[2][0], xb.x, wx, acc[2][0]);
            FMA2(acc[2][1], xb.x, wy, acc[2][1]);
            FMA2(acc[2][2], xb.x, wz, acc[2][2]);
            FMA2(acc[2][3], xb.x, ww, acc[2][3]);
            FMA2(acc[3][0], xb.y, wx, acc[3][0]);
            FMA2(acc[3][1], xb.y, wy, acc[3][1]);
            FMA2(acc[3][2], xb.y, wz, acc[3][2]);
            FMA2(acc[3][3], xb.y, ww, acc[3][3]);
        }
        __syncthreads();
    }

    // destination: interleaved [n][h][c] for W1, per-head [h][n][c] for W2
    float* dst;
    size_t rstride;
    if (isw2) {
        dst = g_feats2 + ((size_t)head * NN + n0 + r0) * CC + c0;
        rstride = CC;
    } else {
        dst = g_featsI + (size_t)(n0 + r0) * (HH * CC) + head * CC + c0;
        rstride = HH * CC;
    }
    const float4 as = *(const float4*)(a_self  + head * CC + c0);
    const float4 an = *(const float4*)(a_neigh + head * CC + c0);

    #pragma unroll
    for (int rp = 0; rp < 4; ++rp) {
        float lo0, hi0, lo1, hi1, lo2, hi2, lo3, hi3;
        UNPACK2(lo0, hi0, acc[rp][0]);
        UNPACK2(lo1, hi1, acc[rp][1]);
        UNPACK2(lo2, hi2, acc[rp][2]);
        UNPACK2(lo3, hi3, acc[rp][3]);
        *(float4*)(dst + (size_t)(2 * rp) * rstride)     = make_float4(lo0, lo1, lo2, lo3);
        *(float4*)(dst + (size_t)(2 * rp + 1) * rstride) = make_float4(hi0, hi1, hi2, hi3);

        if (!isw2) {
            float s0 = lo0 * as.x + lo1 * as.y + lo2 * as.z + lo3 * as.w;
            float t0 = lo0 * an.x + lo1 * an.y + lo2 * an.z + lo3 * an.w;
            float s1 = hi0 * as.x + hi1 * as.y + hi2 * as.z + hi3 * as.w;
            float t1 = hi0 * an.x + hi1 * an.y + hi2 * an.z + hi3 * an.w;
            #pragma unroll
            for (int o = 8; o; o >>= 1) {
                s0 += __shfl_xor_sync(0xffffffffu, s0, o);
                t0 += __shfl_xor_sync(0xffffffffu, t0, o);
                s1 += __shfl_xor_sync(0xffffffffu, s1, o);
                t1 += __shfl_xor_sync(0xffffffffu, t1, o);
            }
            if (tx == 0) {
                ((float*)g_atts4)[(n0 + r0 + 2 * rp) * 4 + head]     = s0;
                ((float*)g_attn4)[(n0 + r0 + 2 * rp) * 4 + head]     = t0;
                ((float*)g_atts4)[(n0 + r0 + 2 * rp + 1) * 4 + head] = s1;
                ((float*)g_attn4)[(n0 + r0 + 2 * rp + 1) * 4 + head] = t1;
            }
        }
    }
}

// ---------------------------------------------------------------------------
// k_attn: R8 structure (grid=NN, 128 thr, high occupancy) with head-
// interleaved gather: a warp loads a neighbor's FULL 1KB 4-head block with
// 2 LDG.128; warps split the neighbor list; cross-warp smem reduce at end.
// ---------------------------------------------------------------------------
__global__ __launch_bounds__(128) void k_attn(
    const float* __restrict__ A,
    const float* __restrict__ bias,
    float* __restrict__ out)
{
    __shared__ int    s_idx[MAXNB];          // byte offsets (col * 1024)
    __shared__ float4 s_e4[MAXNB];           // per-neighbor 4-head weights
    __shared__ int    s_wsum[4];
    __shared__ float  s_redm[4][4];
    __shared__ float  s_reds[4][4];
    __shared__ float  s_part[4][32][8];      // [warp][lane][2 heads x 4 ch]

    const int i    = blockIdx.x;
    const int tid  = threadIdx.x;
    const int lane = tid & 31;
    const int warp = tid >> 5;
    const float* Ai = A + (size_t)i * NN;

    // --- coalesced scan, presence bitmask in a register ---
    ull mask = 0ull;
    #pragma unroll
    for (int k = 0; k < 12; ++k) {
        float4 v = *(const float4*)(Ai + 4 * tid + 512 * k);
        unsigned m = (unsigned)(v.x != 0.f)
                   | ((unsigned)(v.y != 0.f) << 1)
                   | ((unsigned)(v.z != 0.f) << 2)
                   | ((unsigned)(v.w != 0.f) << 3);
        mask |= (ull)m << (4 * k);
    }
    const int lc = __popcll(mask);

    // --- warp shfl scan + cross-warp combine ---
    int v = lc;
    #pragma unroll
    for (int o = 1; o < 32; o <<= 1) {
        int u = __shfl_up_sync(0xffffffffu, v, o);
        if (lane >= o) v += u;
    }
    if (lane == 31) s_wsum[warp] = v;
    __syncthreads();
    int base = 0;
    #pragma unroll
    for (int w = 0; w < 4; ++w)
        if (w < warp) base += s_wsum[w];
    int cnt = s_wsum[0] + s_wsum[1] + s_wsum[2] + s_wsum[3];
    if (cnt > MAXNB) cnt = MAXNB;

    // --- compaction: store BYTE offsets (col << 10 = col * HH * CC * 4) ---
    int p = base + v - lc;
    ull m2 = mask;
    while (m2) {
        int b = __ffsll((long long)m2) - 1;
        m2 &= m2 - 1;
        int col = 4 * tid + 512 * (b >> 2) + (b & 3);
        if (p < MAXNB) s_idx[p] = col << 10;
        ++p;
    }
    __syncthreads();

    // --- logit pass: ONE float4 gather per neighbor serves all 4 heads ---
    const float4 si4 = g_atts4[i];
    float m0 = -1e30f, m1 = -1e30f, m2f = -1e30f, m3 = -1e30f;
    for (int j = tid; j < cnt; j += 128) {
        int off = s_idx[j];
        float4 an = *(const float4*)((const char*)g_attn4 + (off >> 6));
        float l0 = si4.x + an.x;  l0 = (l0 > 0.f) ? l0 : 0.2f * l0;
        float l1 = si4.y + an.y;  l1 = (l1 > 0.f) ? l1 : 0.2f * l1;
        float l2 = si4.z + an.z;  l2 = (l2 > 0.f) ? l2 : 0.2f * l2;
        float l3 = si4.w + an.w;  l3 = (l3 > 0.f) ? l3 : 0.2f * l3;
        s_e4[j] = make_float4(l0, l1, l2, l3);
        m0 = fmaxf(m0, l0);   m1 = fmaxf(m1, l1);
        m2f = fmaxf(m2f, l2); m3 = fmaxf(m3, l3);
    }
    #pragma unroll
    for (int o = 16; o; o >>= 1) {
        m0  = fmaxf(m0,  __shfl_xor_sync(0xffffffffu, m0,  o));
        m1  = fmaxf(m1,  __shfl_xor_sync(0xffffffffu, m1,  o));
        m2f = fmaxf(m2f, __shfl_xor_sync(0xffffffffu, m2f, o));
        m3  = fmaxf(m3,  __shfl_xor_sync(0xffffffffu, m3,  o));
    }
    if (lane == 0)
        *(float4*)&s_redm[warp][0] = make_float4(m0, m1, m2f, m3);
    __syncthreads();
    {
        float4 a = *(float4*)&s_redm[0][0];
        float4 b = *(float4*)&s_redm[1][0];
        float4 c = *(float4*)&s_redm[2][0];
        float4 d = *(float4*)&s_redm[3][0];
        m0  = fmaxf(fmaxf(a.x, b.x), fmaxf(c.x, d.x));
        m1  = fmaxf(fmaxf(a.y, b.y), fmaxf(c.y, d.y));
        m2f = fmaxf(fmaxf(a.z, b.z), fmaxf(c.z, d.z));
        m3  = fmaxf(fmaxf(a.w, b.w), fmaxf(c.w, d.w));
    }

    // --- exp pass (vectorized, smem only) ---
    float q0 = 0.f, q1 = 0.f, q2 = 0.f, q3 = 0.f;
    for (int j = tid; j < cnt; j += 128) {
        float4 e = s_e4[j];
        e.x = __expf(e.x - m0);   q0 += e.x;
        e.y = __expf(e.y - m1);   q1 += e.y;
        e.z = __expf(e.z - m2f);  q2 += e.z;
        e.w = __expf(e.w - m3);   q3 += e.w;
        s_e4[j] = e;
    }
    #pragma unroll
    for (int o = 16; o; o >>= 1) {
        q0 += __shfl_xor_sync(0xffffffffu, q0, o);
        q1 += __shfl_xor_sync(0xffffffffu, q1, o);
        q2 += __shfl_xor_sync(0xffffffffu, q2, o);
        q3 += __shfl_xor_sync(0xffffffffu, q3, o);
    }
    if (lane == 0)
        *(float4*)&s_reds[warp][0] = make_float4(q0, q1, q2, q3);
    __syncthreads();

    const float inv0 = 1.f / (s_reds[0][0] + s_reds[1][0] + s_reds[2][0] + s_reds[3][0]);
    const float inv1 = 1.f / (s_reds[0][1] + s_reds[1][1] + s_reds[2][1] + s_reds[3][1]);
    const float inv2 = 1.f / (s_reds[0][2] + s_reds[1][2] + s_reds[2][2] + s_reds[3][2]);
    const float inv3 = 1.f / (s_reds[0][3] + s_reds[1][3] + s_reds[2][3] + s_reds[3][3]);

    // --- gather: warps split neighbors (j = warp mod 4). Per neighbor, a
    // warp loads the full [h][c] 1KB block as 2 LDG.128/lane:
    //   fa (bytes lane*16):       head = lane/16,     c = (lane%16)*4 ..+3
    //   fb (bytes 512+lane*16):   head = lane/16 + 2, same channels
    const char* fb0 = (const char*)g_featsI;
    float aA0 = 0.f, aA1 = 0.f, aA2 = 0.f, aA3 = 0.f;   // head lane/16
    float aB0 = 0.f, aB1 = 0.f, aB2 = 0.f, aB3 = 0.f;   // head lane/16 + 2
    for (int j = warp; j < cnt; j += 4) {
        const char* nb = fb0 + s_idx[j];
        float4 e4 = s_e4[j];                 // broadcast LDS.128
        float4 fa = *(const float4*)(nb + lane * 16);
        float4 fbv = *(const float4*)(nb + 512 + lane * 16);
        float eA = (lane < 16) ? e4.x : e4.y;
        float eB = (lane < 16) ? e4.z : e4.w;
        aA0 += eA * fa.x;   aA1 += eA * fa.y;
        aA2 += eA * fa.z;   aA3 += eA * fa.w;
        aB0 += eB * fbv.x;  aB1 += eB * fbv.y;
        aB2 += eB * fbv.z;  aB3 += eB * fbv.w;
    }
    const float invA = (lane < 16) ? inv0 : inv1;
    const float invB = (lane < 16) ? inv2 : inv3;
    *(float4*)&s_part[warp][lane][0] = make_float4(aA0 * invA, aA1 * invA, aA2 * invA, aA3 * invA);
    *(float4*)&s_part[warp][lane][4] = make_float4(aB0 * invB, aB1 * invB, aB2 * invB, aB3 * invB);
    __syncthreads();

    // --- combine: thread c (0..63) sums 4 warps x 4 head-slots ---
    if (tid < CC) {
        const int lr = tid >> 2;             // lane row 0..15
        const int k  = tid & 3;
        float s = 0.f;
        #pragma unroll
        for (int w = 0; w < 4; ++w) {
            s += s_part[w][lr][k]      + s_part[w][lr][4 + k]        // heads 0, 2
               + s_part[w][16 + lr][k] + s_part[w][16 + lr][4 + k];  // heads 1, 3
        }
        float b = 0.f;
        #pragma unroll
        for (int hh = 0; hh < HH; ++hh)
            b += g_feats2[((size_t)hh * NN + i) * CC + tid] + bias[hh * CC + tid];
        float o = 0.25f * b + 0.25f * s;
        out[(size_t)i * CC + tid] = (o > 0.f) ? o : 0.f;
    }
}

// ---------------------------------------------------------------------------
extern "C" void kernel_launch(void* const* d_in, const int* in_sizes, int n_in,
                              void* d_out, int out_size)
{
    const float* X       = (const float*)d_in[0];
    const float* A       = (const float*)d_in[1];
    const float* W1      = (const float*)d_in[2];
    const float* W2      = (const float*)d_in[3];
    const float* a_self  = (const float*)d_in[4];
    const float* a_neigh = (const float*)d_in[5];
    const float* bias    = (const float*)d_in[6];
    float* out = (float*)d_out;

    k_proj<<<dim3(48, 8), 256>>>(X, W1, W2, a_self, a_neigh);
    k_attn<<<NN,          128>>>(A, bias, out);
}